// round 13
// baseline (speedup 1.0000x reference)
#include <cuda_runtime.h>
#include <math.h>

#define NH 4
#define NN 1024
#define EE 4096
#define NLE 16384
#define FN 128
#define FE 64
#define NODE_OUT_SZ (NH*NN*FN)   /* 524288 */

// ---------------- scratch (device globals; zero-initialized at load) ----------------
__device__ float g_nv[NN*NH*FN];
__device__ float g_ev[EE*NH*FE];
__device__ float g_nk[NN*NH];          // flat k-linear output [row][c]
__device__ float g_ek[EE*NH];
__device__ float g_yn[NH*512];         // y[h][b*128+f]  (atomics; zeroed each run)
__device__ float g_ye[NH*256];
__device__ float g_ksn[16];            // ks[h][b]       (atomics; zeroed each run)
__device__ float g_kse[16];
__device__ float g_un[NH*512];         // u[h][b*128+j]
__device__ float g_ue[NH*256];
__device__ float g_cn[16];             // c[h][b]
__device__ float g_ce[16];
__device__ float g_nsa[NH*NN];         // softmaxed node attention
__device__ float g_esa[NH*EE];         // softmaxed edge attention
__device__ int   g_cnt_n[NN], g_fc_n[NN], g_off_n[NN+1], g_lst_n[EE];
__device__ int   g_cnt_e[EE], g_fc_e[EE], g_off_e[EE+1], g_lst_e[NLE];
__device__ float g_ncWT[FN*FN];
__device__ float g_ecWT[FE*FE];
__device__ float g_nqWT[FN*512];       // nqWT[j*512+o] = nqW[o*128+j]
__device__ float g_eqWT[FE*256];       // eqWT[j*256+o] = eqW[o*64+j]

__device__ __forceinline__ float wredsum(float v)
{
#pragma unroll
    for (int o = 16; o; o >>= 1) v += __shfl_xor_sync(0xffffffffu, v, o);
    return v;
}

// ---------------- gemm tile: C[64,64] of A[M,K] @ W[N,K]^T + bias ----------------
__device__ __forceinline__
void gemm_tile(const float* __restrict__ A, const float* __restrict__ W,
               const float* __restrict__ bias, float* __restrict__ C,
               int bm, int bn, int Nout, int K)
{
    __shared__ float As[32][64];
    __shared__ float Bs[32][64];
    int tid = threadIdx.x;
    int tx = tid & 15, ty = tid >> 4;

    float acc[4][4];
#pragma unroll
    for (int i = 0; i < 4; i++)
#pragma unroll
        for (int j = 0; j < 4; j++) acc[i][j] = 0.f;

    for (int k0 = 0; k0 < K; k0 += 32) {
#pragma unroll
        for (int j = 0; j < 2; j++) {
            int f4 = tid + j * 256;
            int m  = f4 >> 3;
            int k4 = f4 & 7;
            float4 va = *reinterpret_cast<const float4*>(&A[(size_t)(bm + m) * K + k0 + k4 * 4]);
            As[k4*4+0][m] = va.x; As[k4*4+1][m] = va.y; As[k4*4+2][m] = va.z; As[k4*4+3][m] = va.w;
            float4 vb = *reinterpret_cast<const float4*>(&W[(size_t)(bn + m) * K + k0 + k4 * 4]);
            Bs[k4*4+0][m] = vb.x; Bs[k4*4+1][m] = vb.y; Bs[k4*4+2][m] = vb.z; Bs[k4*4+3][m] = vb.w;
        }
        __syncthreads();
#pragma unroll
        for (int kk = 0; kk < 32; kk++) {
            float4 a = *reinterpret_cast<const float4*>(&As[kk][ty * 4]);
            float4 b = *reinterpret_cast<const float4*>(&Bs[kk][tx * 4]);
            float ra[4] = {a.x, a.y, a.z, a.w};
            float rb[4] = {b.x, b.y, b.z, b.w};
#pragma unroll
            for (int i = 0; i < 4; i++)
#pragma unroll
                for (int j = 0; j < 4; j++) acc[i][j] += ra[i] * rb[j];
        }
        __syncthreads();
    }
#pragma unroll
    for (int i = 0; i < 4; i++) {
        int row = bm + ty * 4 + i;
        int col = bn + tx * 4;
        float4 r;
        r.x = acc[i][0] + bias[col+0];
        r.y = acc[i][1] + bias[col+1];
        r.z = acc[i][2] + bias[col+2];
        r.w = acc[i][3] + bias[col+3];
        *reinterpret_cast<float4*>(&C[(size_t)row * Nout + col]) = r;
    }
}

// ---------------- K1: prep — kproj + counts + transposes + V gemms ----------------
// grid 1504 x 256
__global__ __launch_bounds__(256)
void prep_kernel(const float* __restrict__ node_in, const float* __restrict__ edge_in,
                 const float* __restrict__ nkW, const float* __restrict__ nkb,
                 const float* __restrict__ ekW, const float* __restrict__ ekb,
                 const int* __restrict__ src, const int* __restrict__ lg_src,
                 const float* __restrict__ ncW, const float* __restrict__ ecW,
                 const float* __restrict__ nqW, const float* __restrict__ eqW,
                 const float* __restrict__ nvW, const float* __restrict__ nvb,
                 const float* __restrict__ evW, const float* __restrict__ evb)
{
    int bid = blockIdx.x, tid = threadIdx.x;
    if (bid < 640) {
        int w = bid * 8 + (tid >> 5), lane = tid & 31;
        if (w < NN) {
            float4 xv = reinterpret_cast<const float4*>(node_in + w * FN)[lane];
            float4 w0 = reinterpret_cast<const float4*>(nkW + 0*FN)[lane];
            float4 w1 = reinterpret_cast<const float4*>(nkW + 1*FN)[lane];
            float4 w2 = reinterpret_cast<const float4*>(nkW + 2*FN)[lane];
            float4 w3 = reinterpret_cast<const float4*>(nkW + 3*FN)[lane];
            float p0 = xv.x*w0.x + xv.y*w0.y + xv.z*w0.z + xv.w*w0.w;
            float p1 = xv.x*w1.x + xv.y*w1.y + xv.z*w1.z + xv.w*w1.w;
            float p2 = xv.x*w2.x + xv.y*w2.y + xv.z*w2.z + xv.w*w2.w;
            float p3 = xv.x*w3.x + xv.y*w3.y + xv.z*w3.z + xv.w*w3.w;
            p0 = wredsum(p0); p1 = wredsum(p1); p2 = wredsum(p2); p3 = wredsum(p3);
            if (lane < 4) {
                float v = (lane == 0) ? p0 : (lane == 1) ? p1 : (lane == 2) ? p2 : p3;
                g_nk[w * 4 + lane] = v + nkb[lane];
            }
        } else {
            int row = w - NN;
            float2 xv = reinterpret_cast<const float2*>(edge_in + row * FE)[lane];
            float2 w0 = reinterpret_cast<const float2*>(ekW + 0*FE)[lane];
            float2 w1 = reinterpret_cast<const float2*>(ekW + 1*FE)[lane];
            float2 w2 = reinterpret_cast<const float2*>(ekW + 2*FE)[lane];
            float2 w3 = reinterpret_cast<const float2*>(ekW + 3*FE)[lane];
            float p0 = xv.x*w0.x + xv.y*w0.y;
            float p1 = xv.x*w1.x + xv.y*w1.y;
            float p2 = xv.x*w2.x + xv.y*w2.y;
            float p3 = xv.x*w3.x + xv.y*w3.y;
            p0 = wredsum(p0); p1 = wredsum(p1); p2 = wredsum(p2); p3 = wredsum(p3);
            if (lane < 4) {
                float v = (lane == 0) ? p0 : (lane == 1) ? p1 : (lane == 2) ? p2 : p3;
                g_ek[row * 4 + lane] = v + ekb[lane];
            }
        }
    } else if (bid < 720) {
        int idx = (bid - 640) * 256 + tid;
        if (idx < EE)            atomicAdd(&g_cnt_n[src[idx]], 1);
        else if (idx < EE + NLE) atomicAdd(&g_cnt_e[lg_src[idx - EE]], 1);
    } else if (bid < 1120) {
        int idx = (bid - 720) * 256 + tid;
        if (idx < FN*FN) {
            int o = idx >> 7, f = idx & 127;
            g_ncWT[f*FN + o] = ncW[idx];
        } else if (idx < FN*FN + FE*FE) {
            int i = idx - FN*FN;
            int o = i >> 6, f = i & 63;
            g_ecWT[f*FE + o] = ecW[i];
        } else if (idx < FN*FN + FE*FE + 512*FN) {
            int i = idx - (FN*FN + FE*FE);
            int o = i >> 7, j = i & 127;
            g_nqWT[j*512 + o] = nqW[i];
        } else {
            int i = idx - (FN*FN + FE*FE + 512*FN);
            int o = i >> 6, j = i & 63;
            g_eqWT[j*256 + o] = eqW[i];
        }
    } else {
        int b = bid - 1120;
        if (b < 128) {
            gemm_tile(node_in, nvW, nvb, g_nv, (b >> 3) * 64, (b & 7) * 64, NH*FN, FN);
        } else {
            b -= 128;
            gemm_tile(edge_in, evW, evb, g_ev, (b >> 2) * 64, (b & 3) * 64, NH*FE, FE);
        }
    }
}

// ---------------- K2: scans + wide y/ks reduction ----------------
__device__ void scan256(const int* __restrict__ in, int* __restrict__ out, int items)
{
    __shared__ int sums[256];
    int tid = threadIdx.x;
    int loc[16];
    int s = 0;
    for (int j = 0; j < items; j++) { loc[j] = in[tid * items + j]; s += loc[j]; }
    sums[tid] = s;
    __syncthreads();
    for (int off = 1; off < 256; off <<= 1) {
        int add = (tid >= off) ? sums[tid - off] : 0;
        __syncthreads();
        sums[tid] += add;
        __syncthreads();
    }
    int run = (tid == 0) ? 0 : sums[tid - 1];
    for (int j = 0; j < items; j++) { out[tid * items + j] = run; run += loc[j]; }
    if (tid == 255) out[256 * items] = sums[255];
}

// grid 322 x 256
__global__ __launch_bounds__(256)
void scan_y_kernel(const float* __restrict__ node_in, const float* __restrict__ edge_in)
{
    int bid = blockIdx.x, tid = threadIdx.x;
    if (bid == 0)      { scan256(g_cnt_n, g_off_n, 4);  return; }
    else if (bid == 1) { scan256(g_cnt_e, g_off_e, 16); return; }
    else if (bid < 66) {
        int blk = bid - 2;
        int h = blk >> 4;
        int f = tid & 127, part = tid >> 7;
        int m0 = blk * 16 + part * 8;
        float a0 = 0.f, a1 = 0.f, a2 = 0.f, a3 = 0.f;
        for (int m = m0; m < m0 + 8; m++) {
            float x = node_in[m * FN + f];
            const float* kp = g_nk + m * 4;
            a0 += kp[0]*x; a1 += kp[1]*x; a2 += kp[2]*x; a3 += kp[3]*x;
        }
        atomicAdd(&g_yn[h*512 + 0*FN + f], a0);
        atomicAdd(&g_yn[h*512 + 1*FN + f], a1);
        atomicAdd(&g_yn[h*512 + 2*FN + f], a2);
        atomicAdd(&g_yn[h*512 + 3*FN + f], a3);
        if (f < 4 && part == 0) {
            float s = 0.f;
            for (int m = blk * 16; m < blk * 16 + 16; m++) s += g_nk[m * 4 + f];
            atomicAdd(&g_ksn[h*4 + f], s);
        }
    } else {
        int blk = bid - 66;
        int h = blk >> 6;
        int f = tid & 63, part = tid >> 6;
        int m0 = blk * 16 + part * 4;
        float a0 = 0.f, a1 = 0.f, a2 = 0.f, a3 = 0.f;
        for (int m = m0; m < m0 + 4; m++) {
            float x = edge_in[m * FE + f];
            const float* kp = g_ek + m * 4;
            a0 += kp[0]*x; a1 += kp[1]*x; a2 += kp[2]*x; a3 += kp[3]*x;
        }
        atomicAdd(&g_ye[h*256 + 0*FE + f], a0);
        atomicAdd(&g_ye[h*256 + 1*FE + f], a1);
        atomicAdd(&g_ye[h*256 + 2*FE + f], a2);
        atomicAdd(&g_ye[h*256 + 3*FE + f], a3);
        if (f < 4 && part == 0) {
            float s = 0.f;
            for (int m = blk * 16; m < blk * 16 + 16; m++) s += g_ek[m * 4 + f];
            atomicAdd(&g_kse[h*4 + f], s);
        }
    }
}

// ---------------- K3: CSR fill + fused t->u->c per head ----------------
// grid 28 x 1024: [0,20) fill, [20,24) node heads, [24,28) edge heads
__global__ __launch_bounds__(1024)
void fill_tuc_kernel(const int* __restrict__ src, const int* __restrict__ lg_src,
                     const float* __restrict__ nqW, const float* __restrict__ nqb,
                     const float* __restrict__ eqW, const float* __restrict__ eqb)
{
    int bid = blockIdx.x, tid = threadIdx.x;
    if (bid < 20) {
        int idx = bid * 1024 + tid;       // covers exactly 20480 = EE + NLE
        if (idx < EE) {
            int s = src[idx];
            int p = g_off_n[s] + atomicAdd(&g_fc_n[s], 1);
            g_lst_n[p] = idx;
        } else {
            int l = idx - EE;
            int s = lg_src[l];
            int p = g_off_e[s] + atomicAdd(&g_fc_e[s], 1);
            g_lst_e[p] = l;
        }
        return;
    }
    __shared__ float sy[512];
    __shared__ float st[FN];
    __shared__ float sks[4];
    int warp = tid >> 5, lane = tid & 31;
    if (bid < 24) {
        int h = bid - 20;
        if (tid < 512) sy[tid] = g_yn[h*512 + tid];
        if (tid < 4)   sks[tid] = g_ksn[h*4 + tid];
        __syncthreads();
        // t[f] (warp per f)
        for (int f = warp; f < FN; f += 32) {
            float acc = 0.f;
#pragma unroll
            for (int b = 0; b < 4; b++) {
                float4 wv = *reinterpret_cast<const float4*>(&nqW[(size_t)(b*FN + f) * FN + lane*4]);
                float4 yv = *reinterpret_cast<const float4*>(&sy[b*FN + lane*4]);
                acc += wv.x*yv.x + wv.y*yv.y + wv.z*yv.z + wv.w*yv.w;
            }
            acc = wredsum(acc);
            if (lane == 0) {
                float bt = 0.f;
#pragma unroll
                for (int b = 0; b < 4; b++) bt += nqb[b*FN + f] * sks[b];
                st[f] = acc + bt;
            }
        }
        __syncthreads();
        // u[p] (warp per p, 16 iters)
        for (int p = warp; p < 512; p += 32) {
            int bq = p >> 7, j = p & 127;
            float4 wv = *reinterpret_cast<const float4*>(&g_nqWT[j*512 + bq*FN + lane*4]);
            float4 tv = *reinterpret_cast<const float4*>(&st[lane*4]);
            float acc = wv.x*tv.x + wv.y*tv.y + wv.z*tv.z + wv.w*tv.w;
            acc = wredsum(acc);
            if (lane == 0) g_un[h*512 + p] = acc;
        }
        // c[b] (warps 0..3)
        if (warp < 4) {
            float4 bv = *reinterpret_cast<const float4*>(&nqb[warp*FN + lane*4]);
            float4 tv = *reinterpret_cast<const float4*>(&st[lane*4]);
            float acc = bv.x*tv.x + bv.y*tv.y + bv.z*tv.z + bv.w*tv.w;
            acc = wredsum(acc);
            if (lane == 0) g_cn[h*4 + warp] = acc;
        }
    } else {
        int h = bid - 24;
        if (tid < 256) sy[tid] = g_ye[h*256 + tid];
        if (tid < 4)   sks[tid] = g_kse[h*4 + tid];
        __syncthreads();
        for (int f = warp; f < FE; f += 32) {
            float acc = 0.f;
#pragma unroll
            for (int b = 0; b < 4; b++) {
                float2 wv = *reinterpret_cast<const float2*>(&eqW[(size_t)(b*FE + f) * FE + lane*2]);
                float2 yv = *reinterpret_cast<const float2*>(&sy[b*FE + lane*2]);
                acc += wv.x*yv.x + wv.y*yv.y;
            }
            acc = wredsum(acc);
            if (lane == 0) {
                float bt = 0.f;
#pragma unroll
                for (int b = 0; b < 4; b++) bt += eqb[b*FE + f] * sks[b];
                st[f] = acc + bt;
            }
        }
        __syncthreads();
        for (int p = warp; p < 256; p += 32) {
            int bq = p >> 6, j = p & 63;
            float2 wv = *reinterpret_cast<const float2*>(&g_eqWT[j*256 + bq*FE + lane*2]);
            float2 tv = *reinterpret_cast<const float2*>(&st[lane*2]);
            float acc = wv.x*tv.x + wv.y*tv.y;
            acc = wredsum(acc);
            if (lane == 0) g_ue[h*256 + p] = acc;
        }
        if (warp < 4) {
            float2 bv = *reinterpret_cast<const float2*>(&eqb[warp*FE + lane*2]);
            float2 tv = *reinterpret_cast<const float2*>(&st[lane*2]);
            float acc = bv.x*tv.x + bv.y*tv.y;
            acc = wredsum(acc);
            if (lane == 0) g_ce[h*4 + warp] = acc;
        }
    }
}

// ---------------- K4: fused scores + softmax (block per head) ----------------
// grid 8 x 1024: bids 0..3 node heads, 4..7 edge heads
__global__ __launch_bounds__(1024)
void scores_softmax_kernel(const float* __restrict__ node_in, const float* __restrict__ edge_in)
{
    __shared__ float su[4*132];     // padded u (node: 4x132, edge uses 4x68)
    __shared__ float sc[4];
    __shared__ float red[32];
    __shared__ float bc;
    int bid = blockIdx.x, tid = threadIdx.x;
    int warp = tid >> 5, lane = tid & 31;
    if (bid < 4) {
        int h = bid;
        if (tid < 512) su[(tid >> 7)*132 + (tid & 127)] = g_un[h*512 + tid];
        if (tid < 4)   sc[tid] = g_cn[h*4 + tid];
        __syncthreads();
        int a = tid >> 2, b = tid & 3;
        const float* xr = node_in + (h*256 + a) * FN;
        const float* ur = su + b*132;
        float d = 0.f;
#pragma unroll 8
        for (int j = 0; j < 32; j++) {
            float4 xv = *reinterpret_cast<const float4*>(&xr[j*4]);
            float4 uv = *reinterpret_cast<const float4*>(&ur[j*4]);
            d += xv.x*uv.x + xv.y*uv.y + xv.z*uv.z + xv.w*uv.w;
        }
        d += sc[b];
        // block softmax over 1024 values
        float m = d;
#pragma unroll
        for (int o = 16; o; o >>= 1) m = fmaxf(m, __shfl_xor_sync(0xffffffffu, m, o));
        if (lane == 0) red[warp] = m;
        __syncthreads();
        if (tid == 0) {
            float x = red[0];
            for (int w = 1; w < 32; w++) x = fmaxf(x, red[w]);
            bc = x;
        }
        __syncthreads();
        float e = expf(d - bc);
        float s = wredsum(e);
        __syncthreads();
        if (lane == 0) red[warp] = s;
        __syncthreads();
        if (tid == 0) {
            float x = 0.f;
            for (int w = 0; w < 32; w++) x += red[w];
            bc = x;
        }
        __syncthreads();
        g_nsa[h*NN + tid] = e / bc;
    } else {
        int h = bid - 4;
        if (tid < 256) su[(tid >> 6)*68 + (tid & 63)] = g_ue[h*256 + tid];
        if (tid < 4)   sc[tid] = g_ce[h*4 + tid];
        __syncthreads();
        float v[4];
        float m = -3e38f;
#pragma unroll
        for (int jj = 0; jj < 4; jj++) {
            int mm = tid + jj*1024;
            int a = mm >> 2, b = mm & 3;
            const float* xr = edge_in + (h*1024 + a) * FE;
            const float* ur = su + b*68;
            float d = 0.f;
#pragma unroll 4
            for (int j = 0; j < 16; j++) {
                float4 xv = *reinterpret_cast<const float4*>(&xr[j*4]);
                float4 uv = *reinterpret_cast<const float4*>(&ur[j*4]);
                d += xv.x*uv.x + xv.y*uv.y + xv.z*uv.z + xv.w*uv.w;
            }
            v[jj] = d + sc[b];
            m = fmaxf(m, v[jj]);
        }
#pragma unroll
        for (int o = 16; o; o >>= 1) m = fmaxf(m, __shfl_xor_sync(0xffffffffu, m, o));
        if (lane == 0) red[warp] = m;
        __syncthreads();
        if (tid == 0) {
            float x = red[0];
            for (int w = 1; w < 32; w++) x = fmaxf(x, red[w]);
            bc = x;
        }
        __syncthreads();
        float mx = bc;
        float s = 0.f;
#pragma unroll
        for (int jj = 0; jj < 4; jj++) { v[jj] = expf(v[jj] - mx); s += v[jj]; }
        s = wredsum(s);
        __syncthreads();
        if (lane == 0) red[warp] = s;
        __syncthreads();
        if (tid == 0) {
            float x = 0.f;
            for (int w = 0; w < 32; w++) x += red[w];
            bc = x;
        }
        __syncthreads();
        float inv = 1.f / bc;
#pragma unroll
        for (int jj = 0; jj < 4; jj++) g_esa[h*EE + tid + jj*1024] = v[jj] * inv;
    }
}

// ---------------- K5: outputs (all 4 heads per block; dedup once) + cleanup ----------------
// grid 272 x 256: [0,128) node (8 rows/blk), [128,256) edge (32 rows/blk), [256,272) cleanup
__global__ __launch_bounds__(256)
void out_kernel(const int* __restrict__ dst, const int* __restrict__ lg_dst,
                const float* __restrict__ ncb, const float* __restrict__ ecb,
                float* __restrict__ out)
{
    __shared__ float sm[8192];          // node: agg[4][8][128]; edge: agg[4][32][64]
    int bid = blockIdx.x, tid = threadIdx.x;
    if (bid < 128) {
        int i0 = bid * 8;
        int col = tid & 127, rg = tid >> 7;       // 2 row-groups x 4 rows
#pragma unroll
        for (int k = 0; k < 4; k++) {
            int lr = rg * 4 + k;
            int i = i0 + lr;
            int s0 = g_off_n[i], s1 = g_off_n[i + 1];
            float acc0 = 0.f, acc1 = 0.f, acc2 = 0.f, acc3 = 0.f;
            for (int p = s0; p < s1; p++) {
                int e = g_lst_n[p];
                int d = dst[e];
                bool win = true;
                for (int p2 = s0; p2 < s1; p2++) {
                    int e2 = g_lst_n[p2];
                    if (e2 > e && dst[e2] == d) win = false;   // last write wins
                }
                if (win) {
                    const float* nvp = g_nv + (size_t)d * FN + col;   // g_nv[h][d][col] strided by NN*FN per h
                    acc0 += g_esa[0*EE + e] * nvp[0*(NN*FN)];
                    acc1 += g_esa[1*EE + e] * nvp[1*(NN*FN)];
                    acc2 += g_esa[2*EE + e] * nvp[2*(NN*FN)];
                    acc3 += g_esa[3*EE + e] * nvp[3*(NN*FN)];
                }
            }
            sm[(0*8 + lr)*FN + col] = acc0;
            sm[(1*8 + lr)*FN + col] = acc1;
            sm[(2*8 + lr)*FN + col] = acc2;
            sm[(3*8 + lr)*FN + col] = acc3;
        }
        __syncthreads();
        float bb = ncb[col];
        float accl[4][4];
#pragma unroll
        for (int h = 0; h < 4; h++)
#pragma unroll
            for (int k = 0; k < 4; k++) accl[h][k] = bb;
        for (int f0 = 0; f0 < FN; f0 += 4) {
            float w0 = g_ncWT[(f0+0)*FN + col];
            float w1 = g_ncWT[(f0+1)*FN + col];
            float w2 = g_ncWT[(f0+2)*FN + col];
            float w3 = g_ncWT[(f0+3)*FN + col];
#pragma unroll
            for (int h = 0; h < 4; h++)
#pragma unroll
                for (int k = 0; k < 4; k++) {
                    float4 a4 = *reinterpret_cast<const float4*>(&sm[(h*8 + rg*4 + k)*FN + f0]);
                    accl[h][k] += a4.x*w0 + a4.y*w1 + a4.z*w2 + a4.w*w3;
                }
        }
#pragma unroll
        for (int h = 0; h < 4; h++)
#pragma unroll
            for (int k = 0; k < 4; k++) {
                int i = i0 + rg*4 + k;
                out[(size_t)h*(NN*FN) + (size_t)i*FN + col] = fmaxf(accl[h][k], 0.f);
            }
    } else if (bid < 256) {
        int b2 = bid - 128;
        int i0 = b2 * 32;
        int col = tid & 63, rg = tid >> 6;        // 4 row-groups x 8 rows
#pragma unroll
        for (int k = 0; k < 8; k++) {
            int lr = rg * 8 + k;
            int i = i0 + lr;
            int s0 = g_off_e[i], s1 = g_off_e[i + 1];
            float acc0 = 0.f, acc1 = 0.f, acc2 = 0.f, acc3 = 0.f;
            for (int p = s0; p < s1; p++) {
                int l = g_lst_e[p];
                int ld = lg_dst[l];
                bool win = true;
                for (int p2 = s0; p2 < s1; p2++) {
                    int l2 = g_lst_e[p2];
                    if (l2 > l && lg_dst[l2] == ld) win = false;
                }
                if (win) {
                    const float* evp = g_ev + (size_t)ld * FE + col;
                    acc0 += evp[0*(EE*FE)];
                    acc1 += evp[1*(EE*FE)];
                    acc2 += evp[2*(EE*FE)];
                    acc3 += evp[3*(EE*FE)];
                }
            }
            int dn = dst[i];
            sm[(0*32 + lr)*FE + col] = acc0 * g_nsa[0*NN + dn];
            sm[(1*32 + lr)*FE + col] = acc1 * g_nsa[1*NN + dn];
            sm[(2*32 + lr)*FE + col] = acc2 * g_nsa[2*NN + dn];
            sm[(3*32 + lr)*FE + col] = acc3 * g_nsa[3*NN + dn];
        }
        __syncthreads();
        float bb = ecb[col];
#pragma unroll
        for (int h = 0; h < 4; h++) {
            float a[8];
#pragma unroll
            for (int k = 0; k < 8; k++) a[k] = bb;
            for (int f0 = 0; f0 < FE; f0 += 4) {
                float w0 = g_ecWT[(f0+0)*FE + col];
                float w1 = g_ecWT[(f0+1)*FE + col];
                float w2 = g_ecWT[(f0+2)*FE + col];
                float w3 = g_ecWT[(f0+3)*FE + col];
#pragma unroll
                for (int k = 0; k < 8; k++) {
                    float4 a4 = *reinterpret_cast<const float4*>(&sm[(h*32 + rg*8 + k)*FE + f0]);
                    a[k] += a4.x*w0 + a4.y*w1 + a4.z*w2 + a4.w*w3;
                }
            }
#pragma unroll
            for (int k = 0; k < 8; k++) {
                int i = i0 + rg*8 + k;
                out[NODE_OUT_SZ + (size_t)h*(EE*FE) + (size_t)i*FE + col] = fmaxf(a[k], 0.f);
            }
        }
    } else {
        // cleanup for next run
        int idx = (bid - 256) * 256 + tid;        // 0..4095
        for (int i = idx; i < NN; i += 4096) { g_cnt_n[i] = 0; g_fc_n[i] = 0; }
        for (int i = idx; i < EE; i += 4096) { g_cnt_e[i] = 0; g_fc_e[i] = 0; }
        if (idx < NH*512) g_yn[idx] = 0.f;
        if (idx < NH*256) g_ye[idx] = 0.f;
        if (idx < 16) { g_ksn[idx] = 0.f; g_kse[idx] = 0.f; }
    }
}

// ---------------- launcher ----------------
extern "C" void kernel_launch(void* const* d_in, const int* in_sizes, int n_in,
                              void* d_out, int out_size)
{
    const float* node_inputs = (const float*)d_in[0];
    const float* edge_inputs = (const float*)d_in[1];
    const int*   src         = (const int*)d_in[2];
    const int*   dst         = (const int*)d_in[3];
    const int*   lg_src      = (const int*)d_in[4];
    const int*   lg_dst      = (const int*)d_in[5];
    const float* nqW = (const float*)d_in[6];
    const float* nqb = (const float*)d_in[7];
    const float* nkW = (const float*)d_in[8];
    const float* nkb = (const float*)d_in[9];
    const float* nvW = (const float*)d_in[10];
    const float* nvb = (const float*)d_in[11];
    const float* eqW = (const float*)d_in[12];
    const float* eqb = (const float*)d_in[13];
    const float* ekW = (const float*)d_in[14];
    const float* ekb = (const float*)d_in[15];
    const float* evW = (const float*)d_in[16];
    const float* evb = (const float*)d_in[17];
    const float* ncW = (const float*)d_in[18];
    const float* ncb = (const float*)d_in[19];
    const float* ecW = (const float*)d_in[20];
    const float* ecb = (const float*)d_in[21];
    float* out = (float*)d_out;

    prep_kernel<<<1504, 256>>>(node_inputs, edge_inputs, nkW, nkb, ekW, ekb,
                               src, lg_src, ncW, ecW, nqW, eqW,
                               nvW, nvb, evW, evb);
    scan_y_kernel<<<322, 256>>>(node_inputs, edge_inputs);
    fill_tuc_kernel<<<28, 1024>>>(src, lg_src, nqW, nqb, eqW, eqb);
    scores_softmax_kernel<<<8, 1024>>>(node_inputs, edge_inputs);
    out_kernel<<<272, 256>>>(dst, lg_dst, ncb, ecb, out);
}

// round 15
// speedup vs baseline: 1.0574x; 1.0574x over previous
#include <cuda_runtime.h>
#include <math.h>

#define NH 4
#define NN 1024
#define EE 4096
#define NLE 16384
#define FN 128
#define FE 64
#define NODE_OUT_SZ (NH*NN*FN)   /* 524288 */

// ---------------- scratch (device globals; zero-initialized at load) ----------------
__device__ float g_nv[NN*NH*FN];
__device__ float g_ev[EE*NH*FE];
__device__ float g_nk[NN*NH];          // flat k-linear output [row][c]
__device__ float g_ek[EE*NH];
__device__ float g_yn[NH*512];         // y[h][b*128+f]  (atomics; zeroed each run)
__device__ float g_ye[NH*256];
__device__ float g_ksn[16];            // ks[h][b]       (atomics; zeroed each run)
__device__ float g_kse[16];
__device__ float g_un[NH*512];         // u[h][b*128+j]
__device__ float g_ue[NH*256];
__device__ float g_cn[16];             // c[h][b]
__device__ float g_ce[16];
__device__ float g_nsa[NH*NN];         // scores then softmaxed in place
__device__ float g_esa[NH*EE];
__device__ int   g_cnt_n[NN], g_fc_n[NN], g_off_n[NN+1], g_lst_n[EE];
__device__ int   g_cnt_e[EE], g_fc_e[EE], g_off_e[EE+1], g_lst_e[NLE];
__device__ float g_ncWT[FN*FN];
__device__ float g_ecWT[FE*FE];
__device__ float g_nqWT[FN*512];       // nqWT[j*512+o] = nqW[o*128+j]
__device__ float g_eqWT[FE*256];       // eqWT[j*256+o] = eqW[o*64+j]

__device__ __forceinline__ float wredsum(float v)
{
#pragma unroll
    for (int o = 16; o; o >>= 1) v += __shfl_xor_sync(0xffffffffu, v, o);
    return v;
}

// ---------------- gemm tile: C[64,64] of A[M,K] @ W[N,K]^T + bias ----------------
__device__ __forceinline__
void gemm_tile(const float* __restrict__ A, const float* __restrict__ W,
               const float* __restrict__ bias, float* __restrict__ C,
               int bm, int bn, int Nout, int K)
{
    __shared__ float As[32][64];
    __shared__ float Bs[32][64];
    int tid = threadIdx.x;
    int tx = tid & 15, ty = tid >> 4;

    float acc[4][4];
#pragma unroll
    for (int i = 0; i < 4; i++)
#pragma unroll
        for (int j = 0; j < 4; j++) acc[i][j] = 0.f;

    for (int k0 = 0; k0 < K; k0 += 32) {
#pragma unroll
        for (int j = 0; j < 2; j++) {
            int f4 = tid + j * 256;
            int m  = f4 >> 3;
            int k4 = f4 & 7;
            float4 va = *reinterpret_cast<const float4*>(&A[(size_t)(bm + m) * K + k0 + k4 * 4]);
            As[k4*4+0][m] = va.x; As[k4*4+1][m] = va.y; As[k4*4+2][m] = va.z; As[k4*4+3][m] = va.w;
            float4 vb = *reinterpret_cast<const float4*>(&W[(size_t)(bn + m) * K + k0 + k4 * 4]);
            Bs[k4*4+0][m] = vb.x; Bs[k4*4+1][m] = vb.y; Bs[k4*4+2][m] = vb.z; Bs[k4*4+3][m] = vb.w;
        }
        __syncthreads();
#pragma unroll
        for (int kk = 0; kk < 32; kk++) {
            float4 a = *reinterpret_cast<const float4*>(&As[kk][ty * 4]);
            float4 b = *reinterpret_cast<const float4*>(&Bs[kk][tx * 4]);
            float ra[4] = {a.x, a.y, a.z, a.w};
            float rb[4] = {b.x, b.y, b.z, b.w};
#pragma unroll
            for (int i = 0; i < 4; i++)
#pragma unroll
                for (int j = 0; j < 4; j++) acc[i][j] += ra[i] * rb[j];
        }
        __syncthreads();
    }
#pragma unroll
    for (int i = 0; i < 4; i++) {
        int row = bm + ty * 4 + i;
        int col = bn + tx * 4;
        float4 r;
        r.x = acc[i][0] + bias[col+0];
        r.y = acc[i][1] + bias[col+1];
        r.z = acc[i][2] + bias[col+2];
        r.w = acc[i][3] + bias[col+3];
        *reinterpret_cast<float4*>(&C[(size_t)row * Nout + col]) = r;
    }
}

// ---------------- K1: prep — kproj + counts + transposes + V gemms ----------------
// grid 1504 x 256: [0,640) kproj warps, [640,720) counts, [720,1120) transposes, [1120,1504) V gemms
__global__ __launch_bounds__(256)
void prep_kernel(const float* __restrict__ node_in, const float* __restrict__ edge_in,
                 const float* __restrict__ nkW, const float* __restrict__ nkb,
                 const float* __restrict__ ekW, const float* __restrict__ ekb,
                 const int* __restrict__ src, const int* __restrict__ lg_src,
                 const float* __restrict__ ncW, const float* __restrict__ ecW,
                 const float* __restrict__ nqW, const float* __restrict__ eqW,
                 const float* __restrict__ nvW, const float* __restrict__ nvb,
                 const float* __restrict__ evW, const float* __restrict__ evb)
{
    int bid = blockIdx.x, tid = threadIdx.x;
    if (bid < 640) {
        int w = bid * 8 + (tid >> 5), lane = tid & 31;
        if (w < NN) {
            float4 xv = reinterpret_cast<const float4*>(node_in + w * FN)[lane];
            float4 w0 = reinterpret_cast<const float4*>(nkW + 0*FN)[lane];
            float4 w1 = reinterpret_cast<const float4*>(nkW + 1*FN)[lane];
            float4 w2 = reinterpret_cast<const float4*>(nkW + 2*FN)[lane];
            float4 w3 = reinterpret_cast<const float4*>(nkW + 3*FN)[lane];
            float p0 = xv.x*w0.x + xv.y*w0.y + xv.z*w0.z + xv.w*w0.w;
            float p1 = xv.x*w1.x + xv.y*w1.y + xv.z*w1.z + xv.w*w1.w;
            float p2 = xv.x*w2.x + xv.y*w2.y + xv.z*w2.z + xv.w*w2.w;
            float p3 = xv.x*w3.x + xv.y*w3.y + xv.z*w3.z + xv.w*w3.w;
            p0 = wredsum(p0); p1 = wredsum(p1); p2 = wredsum(p2); p3 = wredsum(p3);
            if (lane < 4) {
                float v = (lane == 0) ? p0 : (lane == 1) ? p1 : (lane == 2) ? p2 : p3;
                g_nk[w * 4 + lane] = v + nkb[lane];
            }
        } else {
            int row = w - NN;
            float2 xv = reinterpret_cast<const float2*>(edge_in + row * FE)[lane];
            float2 w0 = reinterpret_cast<const float2*>(ekW + 0*FE)[lane];
            float2 w1 = reinterpret_cast<const float2*>(ekW + 1*FE)[lane];
            float2 w2 = reinterpret_cast<const float2*>(ekW + 2*FE)[lane];
            float2 w3 = reinterpret_cast<const float2*>(ekW + 3*FE)[lane];
            float p0 = xv.x*w0.x + xv.y*w0.y;
            float p1 = xv.x*w1.x + xv.y*w1.y;
            float p2 = xv.x*w2.x + xv.y*w2.y;
            float p3 = xv.x*w3.x + xv.y*w3.y;
            p0 = wredsum(p0); p1 = wredsum(p1); p2 = wredsum(p2); p3 = wredsum(p3);
            if (lane < 4) {
                float v = (lane == 0) ? p0 : (lane == 1) ? p1 : (lane == 2) ? p2 : p3;
                g_ek[row * 4 + lane] = v + ekb[lane];
            }
        }
    } else if (bid < 720) {
        int idx = (bid - 640) * 256 + tid;
        if (idx < EE)            atomicAdd(&g_cnt_n[src[idx]], 1);
        else if (idx < EE + NLE) atomicAdd(&g_cnt_e[lg_src[idx - EE]], 1);
    } else if (bid < 1120) {
        int idx = (bid - 720) * 256 + tid;     // 0..102399
        if (idx < FN*FN) {
            int o = idx >> 7, f = idx & 127;
            g_ncWT[f*FN + o] = ncW[idx];
        } else if (idx < FN*FN + FE*FE) {
            int i = idx - FN*FN;
            int o = i >> 6, f = i & 63;
            g_ecWT[f*FE + o] = ecW[i];
        } else if (idx < FN*FN + FE*FE + 512*FN) {
            int i = idx - (FN*FN + FE*FE);
            int o = i >> 7, j = i & 127;
            g_nqWT[j*512 + o] = nqW[i];
        } else {
            int i = idx - (FN*FN + FE*FE + 512*FN);
            int o = i >> 6, j = i & 63;
            g_eqWT[j*256 + o] = eqW[i];
        }
    } else {
        int b = bid - 1120;
        if (b < 128) {
            gemm_tile(node_in, nvW, nvb, g_nv, (b >> 3) * 64, (b & 7) * 64, NH*FN, FN);
        } else {
            b -= 128;
            gemm_tile(edge_in, evW, evb, g_ev, (b >> 2) * 64, (b & 3) * 64, NH*FE, FE);
        }
    }
}

// ---------------- K2: scans + y/ks (R5's low-contention layout) ----------------
__device__ void scan_impl(const int* __restrict__ in, int* __restrict__ out, int items)
{
    __shared__ int sums[1024];
    int tid = threadIdx.x;
    int loc[4];
    int s = 0;
#pragma unroll
    for (int j = 0; j < 4; j++) {
        loc[j] = (j < items) ? in[tid * items + j] : 0;
        s += (j < items) ? loc[j] : 0;
    }
    sums[tid] = s;
    __syncthreads();
    for (int off = 1; off < 1024; off <<= 1) {
        int add = (tid >= off) ? sums[tid - off] : 0;
        __syncthreads();
        sums[tid] += add;
        __syncthreads();
    }
    int run = (tid == 0) ? 0 : sums[tid - 1];
    for (int j = 0; j < items; j++) {
        out[tid * items + j] = run;
        run += loc[j];
    }
    if (tid == 1023) out[1024 * items] = sums[1023];
}

// grid 42 x 1024: bid 0 node scan, bid 1 edge scan, 2..9 node-y, 10..41 edge-y
__global__ __launch_bounds__(1024)
void scan_y_kernel(const float* __restrict__ node_in, const float* __restrict__ edge_in)
{
    int bid = blockIdx.x, tid = threadIdx.x;
    if (bid == 0)      scan_impl(g_cnt_n, g_off_n, 1);
    else if (bid == 1) scan_impl(g_cnt_e, g_off_e, 4);
    else if (bid < 10) {
        int chunk = bid - 2;
        int h = chunk >> 1;
        int f = tid & 127, part = tid >> 7;
        int m0 = chunk * 128 + part * 16;
        float a0 = 0.f, a1 = 0.f, a2 = 0.f, a3 = 0.f;
        for (int m = m0; m < m0 + 16; m++) {
            float x = node_in[m * FN + f];
            const float* kp = g_nk + m * 4;
            a0 += kp[0]*x; a1 += kp[1]*x; a2 += kp[2]*x; a3 += kp[3]*x;
        }
        atomicAdd(&g_yn[h*512 + 0*FN + f], a0);
        atomicAdd(&g_yn[h*512 + 1*FN + f], a1);
        atomicAdd(&g_yn[h*512 + 2*FN + f], a2);
        atomicAdd(&g_yn[h*512 + 3*FN + f], a3);
        if (f < 4) {
            float s = 0.f;
            for (int m = m0; m < m0 + 16; m++) s += g_nk[m * 4 + f];
            atomicAdd(&g_ksn[h*4 + f], s);
        }
    } else {
        int chunk = bid - 10;
        int h = chunk >> 3;
        int f = tid & 63, part = tid >> 6;
        int m0 = chunk * 128 + part * 8;
        float a0 = 0.f, a1 = 0.f, a2 = 0.f, a3 = 0.f;
        for (int m = m0; m < m0 + 8; m++) {
            float x = edge_in[m * FE + f];
            const float* kp = g_ek + m * 4;
            a0 += kp[0]*x; a1 += kp[1]*x; a2 += kp[2]*x; a3 += kp[3]*x;
        }
        atomicAdd(&g_ye[h*256 + 0*FE + f], a0);
        atomicAdd(&g_ye[h*256 + 1*FE + f], a1);
        atomicAdd(&g_ye[h*256 + 2*FE + f], a2);
        atomicAdd(&g_ye[h*256 + 3*FE + f], a3);
        if (f < 4) {
            float s = 0.f;
            for (int m = m0; m < m0 + 8; m++) s += g_ek[m * 4 + f];
            atomicAdd(&g_kse[h*4 + f], s);
        }
    }
}

// ---------------- K3: CSR fill + fused t->u->c per head ----------------
// grid 28 x 1024: [0,20) fill, [20,24) node heads, [24,28) edge heads
__global__ __launch_bounds__(1024)
void fill_tuc_kernel(const int* __restrict__ src, const int* __restrict__ lg_src,
                     const float* __restrict__ nqW, const float* __restrict__ nqb,
                     const float* __restrict__ eqW, const float* __restrict__ eqb)
{
    int bid = blockIdx.x, tid = threadIdx.x;
    if (bid < 20) {
        int idx = bid * 1024 + tid;       // covers exactly 20480 = EE + NLE
        if (idx < EE) {
            int s = src[idx];
            int p = g_off_n[s] + atomicAdd(&g_fc_n[s], 1);
            g_lst_n[p] = idx;
        } else {
            int l = idx - EE;
            int s = lg_src[l];
            int p = g_off_e[s] + atomicAdd(&g_fc_e[s], 1);
            g_lst_e[p] = l;
        }
        return;
    }
    __shared__ float sy[512];
    __shared__ float st[FN];
    __shared__ float sks[4];
    int warp = tid >> 5, lane = tid & 31;
    if (bid < 24) {
        int h = bid - 20;
        if (tid < 512) sy[tid] = g_yn[h*512 + tid];
        if (tid < 4)   sks[tid] = g_ksn[h*4 + tid];
        __syncthreads();
        // t[f] (warp per f)
        for (int f = warp; f < FN; f += 32) {
            float acc = 0.f;
#pragma unroll
            for (int b = 0; b < 4; b++) {
                float4 wv = *reinterpret_cast<const float4*>(&nqW[(size_t)(b*FN + f) * FN + lane*4]);
                float4 yv = *reinterpret_cast<const float4*>(&sy[b*FN + lane*4]);
                acc += wv.x*yv.x + wv.y*yv.y + wv.z*yv.z + wv.w*yv.w;
            }
            acc = wredsum(acc);
            if (lane == 0) {
                float bt = 0.f;
#pragma unroll
                for (int b = 0; b < 4; b++) bt += nqb[b*FN + f] * sks[b];
                st[f] = acc + bt;
            }
        }
        __syncthreads();
        // u[p] (warp per p)
        for (int p = warp; p < 512; p += 32) {
            int bq = p >> 7, j = p & 127;
            float4 wv = *reinterpret_cast<const float4*>(&g_nqWT[j*512 + bq*FN + lane*4]);
            float4 tv = *reinterpret_cast<const float4*>(&st[lane*4]);
            float acc = wv.x*tv.x + wv.y*tv.y + wv.z*tv.z + wv.w*tv.w;
            acc = wredsum(acc);
            if (lane == 0) g_un[h*512 + p] = acc;
        }
        // c[b] (warps 0..3)
        if (warp < 4) {
            float4 bv = *reinterpret_cast<const float4*>(&nqb[warp*FN + lane*4]);
            float4 tv = *reinterpret_cast<const float4*>(&st[lane*4]);
            float acc = bv.x*tv.x + bv.y*tv.y + bv.z*tv.z + bv.w*tv.w;
            acc = wredsum(acc);
            if (lane == 0) g_cn[h*4 + warp] = acc;
        }
    } else {
        int h = bid - 24;
        if (tid < 256) sy[tid] = g_ye[h*256 + tid];
        if (tid < 4)   sks[tid] = g_kse[h*4 + tid];
        __syncthreads();
        for (int f = warp; f < FE; f += 32) {
            float acc = 0.f;
#pragma unroll
            for (int b = 0; b < 4; b++) {
                float2 wv = *reinterpret_cast<const float2*>(&eqW[(size_t)(b*FE + f) * FE + lane*2]);
                float2 yv = *reinterpret_cast<const float2*>(&sy[b*FE + lane*2]);
                acc += wv.x*yv.x + wv.y*yv.y;
            }
            acc = wredsum(acc);
            if (lane == 0) {
                float bt = 0.f;
#pragma unroll
                for (int b = 0; b < 4; b++) bt += eqb[b*FE + f] * sks[b];
                st[f] = acc + bt;
            }
        }
        __syncthreads();
        for (int p = warp; p < 256; p += 32) {
            int bq = p >> 6, j = p & 63;
            float2 wv = *reinterpret_cast<const float2*>(&g_eqWT[j*256 + bq*FE + lane*2]);
            float2 tv = *reinterpret_cast<const float2*>(&st[lane*2]);
            float acc = wv.x*tv.x + wv.y*tv.y;
            acc = wredsum(acc);
            if (lane == 0) g_ue[h*256 + p] = acc;
        }
        if (warp < 4) {
            float2 bv = *reinterpret_cast<const float2*>(&eqb[warp*FE + lane*2]);
            float2 tv = *reinterpret_cast<const float2*>(&st[lane*2]);
            float acc = bv.x*tv.x + bv.y*tv.y;
            acc = wredsum(acc);
            if (lane == 0) g_ce[h*4 + warp] = acc;
        }
    }
}

// ---------------- K4: raw scores (wide, one warp per row) ----------------
__global__ __launch_bounds__(256)
void scores_kernel(const float* __restrict__ node_in, const float* __restrict__ edge_in)
{
    int w = blockIdx.x * 8 + (threadIdx.x >> 5);
    int lane = threadIdx.x & 31;
    if (w < NH*NN) {
        int h = w >> 10, m = w & (NN - 1);
        int a = m >> 2, b = m & 3;
        int row = h * 256 + a;
        float4 uv = *reinterpret_cast<const float4*>(&g_un[h*512 + b*FN + lane*4]);
        float4 xv = *reinterpret_cast<const float4*>(&node_in[row*FN + lane*4]);
        float d = xv.x*uv.x + xv.y*uv.y + xv.z*uv.z + xv.w*uv.w;
        d = wredsum(d);
        if (lane == 0) g_nsa[h*NN + m] = d + g_cn[h*4+b];
    } else {
        int w2 = w - NH*NN;
        int h = w2 >> 12, m = w2 & (EE - 1);
        int a = m >> 2, b = m & 3;
        int row = h * 1024 + a;
        float2 uv = *reinterpret_cast<const float2*>(&g_ue[h*256 + b*FE + lane*2]);
        float2 xv = *reinterpret_cast<const float2*>(&edge_in[row*FE + lane*2]);
        float d = xv.x*uv.x + xv.y*uv.y;
        d = wredsum(d);
        if (lane == 0) g_esa[h*EE + m] = d + g_ce[h*4+b];
    }
}

// ---------------- K5: per-head softmax normalize (in place) ----------------
__global__ __launch_bounds__(1024)
void softmax_kernel()
{
    __shared__ float red[32];
    __shared__ float bc_max, bc_sum;
    int bid = blockIdx.x, tid = threadIdx.x;
    int warp = tid >> 5, lane = tid & 31;
    float* buf; int cnt;
    if (bid < 4) { buf = g_nsa + bid * NN;       cnt = 1; }
    else         { buf = g_esa + (bid - 4) * EE; cnt = 4; }

    float v[4];
    float m = -3e38f;
    for (int j = 0; j < cnt; j++) { v[j] = buf[tid + j*1024]; m = fmaxf(m, v[j]); }
#pragma unroll
    for (int o = 16; o; o >>= 1) m = fmaxf(m, __shfl_xor_sync(0xffffffffu, m, o));
    if (lane == 0) red[warp] = m;
    __syncthreads();
    if (tid == 0) {
        float x = red[0];
        for (int w = 1; w < 32; w++) x = fmaxf(x, red[w]);
        bc_max = x;
    }
    __syncthreads();
    float mx = bc_max;

    float sum = 0.f;
    for (int j = 0; j < cnt; j++) { v[j] = expf(v[j] - mx); sum += v[j]; }
#pragma unroll
    for (int o = 16; o; o >>= 1) sum += __shfl_xor_sync(0xffffffffu, sum, o);
    __syncthreads();
    if (lane == 0) red[warp] = sum;
    __syncthreads();
    if (tid == 0) {
        float x = 0.f;
        for (int w = 0; w < 32; w++) x += red[w];
        bc_sum = x;
    }
    __syncthreads();
    float inv = 1.f / bc_sum;
    for (int j = 0; j < cnt; j++) buf[tid + j*1024] = v[j] * inv;
}

// ---------------- K6: merged outputs + cleanup (R5's proven layout) ----------------
// grid 2064 x 128: [0,1024) node (4 rows/blk), [1024,2048) edge (16 rows/blk), [2048,2064) cleanup
__global__ __launch_bounds__(128)
void out_kernel(const int* __restrict__ dst, const int* __restrict__ lg_dst,
                const float* __restrict__ ncb, const float* __restrict__ ecb,
                float* __restrict__ out)
{
    int bid = blockIdx.x, tid = threadIdx.x;
    if (bid < 1024) {
        __shared__ float agg[4][FN];
        int h = bid >> 8;
        int i0 = (bid & 255) * 4;
#pragma unroll
        for (int r = 0; r < 4; r++) {
            int i = i0 + r;
            int s0 = g_off_n[i], s1 = g_off_n[i + 1];
            float acc = 0.f;
            for (int p = s0; p < s1; p++) {
                int e = g_lst_n[p];
                int d = dst[e];
                bool win = true;
                for (int p2 = s0; p2 < s1; p2++) {
                    int e2 = g_lst_n[p2];
                    if (e2 > e && dst[e2] == d) win = false;   // last write wins
                }
                if (win) acc += g_esa[h*EE + e] * g_nv[h*(NN*FN) + d*FN + tid];
            }
            agg[r][tid] = acc;
        }
        __syncthreads();
        float b = ncb[tid];
        float a0 = b, a1 = b, a2 = b, a3 = b;
#pragma unroll 4
        for (int f = 0; f < FN; f++) {
            float w = g_ncWT[f*FN + tid];
            a0 += agg[0][f] * w;
            a1 += agg[1][f] * w;
            a2 += agg[2][f] * w;
            a3 += agg[3][f] * w;
        }
        float* o = out + h*(NN*FN) + i0*FN + tid;
        o[0*FN] = fmaxf(a0, 0.f);
        o[1*FN] = fmaxf(a1, 0.f);
        o[2*FN] = fmaxf(a2, 0.f);
        o[3*FN] = fmaxf(a3, 0.f);
    } else if (bid < 2048) {
        __shared__ float agg[16][FE];
        int b = bid - 1024;
        int h = b >> 8;
        int i0 = (b & 255) * 16;
        int col = tid & 63, rg = tid >> 6;
#pragma unroll
        for (int k = 0; k < 8; k++) {
            int lr = rg * 8 + k;
            int i = i0 + lr;
            int s0 = g_off_e[i], s1 = g_off_e[i + 1];
            float acc = 0.f;
            for (int p = s0; p < s1; p++) {
                int l = g_lst_e[p];
                int ld = lg_dst[l];
                bool win = true;
                for (int p2 = s0; p2 < s1; p2++) {
                    int l2 = g_lst_e[p2];
                    if (l2 > l && lg_dst[l2] == ld) win = false;
                }
                if (win) acc += g_ev[h*(EE*FE) + ld*FE + col];
            }
            acc *= g_nsa[h*NN + dst[i]];
            agg[lr][col] = acc;
        }
        __syncthreads();
        float a[8];
        float bb = ecb[col];
#pragma unroll
        for (int k = 0; k < 8; k++) a[k] = bb;
#pragma unroll 4
        for (int f = 0; f < FE; f++) {
            float w = g_ecWT[f*FE + col];
#pragma unroll
            for (int k = 0; k < 8; k++) a[k] += agg[rg*8 + k][f] * w;
        }
#pragma unroll
        for (int k = 0; k < 8; k++) {
            int i = i0 + rg*8 + k;
            out[NODE_OUT_SZ + h*(EE*FE) + i*FE + col] = fmaxf(a[k], 0.f);
        }
    } else {
        // cleanup for next run
        int idx = (bid - 2048) * 128 + tid;       // 0..2047
        for (int i = idx; i < NN; i += 2048) { g_cnt_n[i] = 0; g_fc_n[i] = 0; }
        for (int i = idx; i < EE; i += 2048) { g_cnt_e[i] = 0; g_fc_e[i] = 0; }
        if (idx < NH*512) g_yn[idx] = 0.f;
        if (idx < NH*256) g_ye[idx] = 0.f;
        if (idx < 16) { g_ksn[idx] = 0.f; g_kse[idx] = 0.f; }
    }
}

// ---------------- launcher ----------------
extern "C" void kernel_launch(void* const* d_in, const int* in_sizes, int n_in,
                              void* d_out, int out_size)
{
    const float* node_inputs = (const float*)d_in[0];
    const float* edge_inputs = (const float*)d_in[1];
    const int*   src         = (const int*)d_in[2];
    const int*   dst         = (const int*)d_in[3];
    const int*   lg_src      = (const int*)d_in[4];
    const int*   lg_dst      = (const int*)d_in[5];
    const float* nqW = (const float*)d_in[6];
    const float* nqb = (const float*)d_in[7];
    const float* nkW = (const float*)d_in[8];
    const float* nkb = (const float*)d_in[9];
    const float* nvW = (const float*)d_in[10];
    const float* nvb = (const float*)d_in[11];
    const float* eqW = (const float*)d_in[12];
    const float* eqb = (const float*)d_in[13];
    const float* ekW = (const float*)d_in[14];
    const float* ekb = (const float*)d_in[15];
    const float* evW = (const float*)d_in[16];
    const float* evb = (const float*)d_in[17];
    const float* ncW = (const float*)d_in[18];
    const float* ncb = (const float*)d_in[19];
    const float* ecW = (const float*)d_in[20];
    const float* ecb = (const float*)d_in[21];
    float* out = (float*)d_out;

    prep_kernel<<<1504, 256>>>(node_inputs, edge_inputs, nkW, nkb, ekW, ekb,
                               src, lg_src, ncW, ecW, nqW, eqW,
                               nvW, nvb, evW, evb);
    scan_y_kernel<<<42, 1024>>>(node_inputs, edge_inputs);
    fill_tuc_kernel<<<28, 1024>>>(src, lg_src, nqW, nqb, eqW, eqb);
    scores_kernel<<<2560, 256>>>(node_inputs, edge_inputs);
    softmax_kernel<<<8, 1024>>>();
    out_kernel<<<2064, 128>>>(dst, lg_dst, ncb, ecb, out);
}

// round 16
// speedup vs baseline: 1.3017x; 1.2311x over previous
#include <cuda_runtime.h>
#include <math.h>

#define NH 4
#define NN 1024
#define EE 4096
#define NLE 16384
#define FN 128
#define FE 64
#define NODE_OUT_SZ (NH*NN*FN)   /* 524288 */

// ---------------- scratch (device globals; zero-initialized at load) ----------------
__device__ float g_nv[NN*NH*FN];
__device__ float g_ev[EE*NH*FE];
__device__ float g_nk[NN*NH];          // flat k-linear output [row][c]
__device__ float g_ek[EE*NH];
__device__ float g_yn[NH*512];         // y[h][b*128+f]  (atomics; zeroed each run)
__device__ float g_ye[NH*256];
__device__ float g_ksn[16];            // ks[h][b]       (atomics; zeroed each run)
__device__ float g_kse[16];
__device__ float g_tn[NH*FN];          // t[h][f]
__device__ float g_te[NH*FE];
__device__ float g_un[NH*512];         // u[h][b*128+j]
__device__ float g_ue[NH*256];
__device__ float g_cn[16];             // c[h][b]
__device__ float g_ce[16];
__device__ float g_nsa[NH*NN];         // scores then softmaxed in place
__device__ float g_esa[NH*EE];
__device__ int   g_cnt_n[NN], g_fc_n[NN], g_off_n[NN+1], g_lst_n[EE];
__device__ int   g_cnt_e[EE], g_fc_e[EE], g_off_e[EE+1], g_lst_e[NLE];
__device__ float g_ncWT[FN*FN];
__device__ float g_ecWT[FE*FE];
__device__ float g_nqWT[FN*512];       // nqWT[j*512+o] = nqW[o*128+j]
__device__ float g_eqWT[FE*256];       // eqWT[j*256+o] = eqW[o*64+j]

__device__ __forceinline__ float wredsum(float v)
{
#pragma unroll
    for (int o = 16; o; o >>= 1) v += __shfl_xor_sync(0xffffffffu, v, o);
    return v;
}

// ---------------- gemm tile: C[64,64] of A[M,K] @ W[N,K]^T + bias ----------------
__device__ __forceinline__
void gemm_tile(const float* __restrict__ A, const float* __restrict__ W,
               const float* __restrict__ bias, float* __restrict__ C,
               int bm, int bn, int Nout, int K)
{
    __shared__ float As[32][64];
    __shared__ float Bs[32][64];
    int tid = threadIdx.x;
    int tx = tid & 15, ty = tid >> 4;

    float acc[4][4];
#pragma unroll
    for (int i = 0; i < 4; i++)
#pragma unroll
        for (int j = 0; j < 4; j++) acc[i][j] = 0.f;

    for (int k0 = 0; k0 < K; k0 += 32) {
#pragma unroll
        for (int j = 0; j < 2; j++) {
            int f4 = tid + j * 256;
            int m  = f4 >> 3;
            int k4 = f4 & 7;
            float4 va = *reinterpret_cast<const float4*>(&A[(size_t)(bm + m) * K + k0 + k4 * 4]);
            As[k4*4+0][m] = va.x; As[k4*4+1][m] = va.y; As[k4*4+2][m] = va.z; As[k4*4+3][m] = va.w;
            float4 vb = *reinterpret_cast<const float4*>(&W[(size_t)(bn + m) * K + k0 + k4 * 4]);
            Bs[k4*4+0][m] = vb.x; Bs[k4*4+1][m] = vb.y; Bs[k4*4+2][m] = vb.z; Bs[k4*4+3][m] = vb.w;
        }
        __syncthreads();
#pragma unroll
        for (int kk = 0; kk < 32; kk++) {
            float4 a = *reinterpret_cast<const float4*>(&As[kk][ty * 4]);
            float4 b = *reinterpret_cast<const float4*>(&Bs[kk][tx * 4]);
            float ra[4] = {a.x, a.y, a.z, a.w};
            float rb[4] = {b.x, b.y, b.z, b.w};
#pragma unroll
            for (int i = 0; i < 4; i++)
#pragma unroll
                for (int j = 0; j < 4; j++) acc[i][j] += ra[i] * rb[j];
        }
        __syncthreads();
    }
#pragma unroll
    for (int i = 0; i < 4; i++) {
        int row = bm + ty * 4 + i;
        int col = bn + tx * 4;
        float4 r;
        r.x = acc[i][0] + bias[col+0];
        r.y = acc[i][1] + bias[col+1];
        r.z = acc[i][2] + bias[col+2];
        r.w = acc[i][3] + bias[col+3];
        *reinterpret_cast<float4*>(&C[(size_t)row * Nout + col]) = r;
    }
}

// ---------------- s0-K1: prep — kproj warps + CSR counts (720 blocks) ----------------
__global__ __launch_bounds__(256)
void prep_kernel(const float* __restrict__ node_in, const float* __restrict__ edge_in,
                 const float* __restrict__ nkW, const float* __restrict__ nkb,
                 const float* __restrict__ ekW, const float* __restrict__ ekb,
                 const int* __restrict__ src, const int* __restrict__ lg_src)
{
    int bid = blockIdx.x, tid = threadIdx.x;
    if (bid < 640) {
        int w = bid * 8 + (tid >> 5), lane = tid & 31;
        if (w < NN) {
            float4 xv = reinterpret_cast<const float4*>(node_in + w * FN)[lane];
            float4 w0 = reinterpret_cast<const float4*>(nkW + 0*FN)[lane];
            float4 w1 = reinterpret_cast<const float4*>(nkW + 1*FN)[lane];
            float4 w2 = reinterpret_cast<const float4*>(nkW + 2*FN)[lane];
            float4 w3 = reinterpret_cast<const float4*>(nkW + 3*FN)[lane];
            float p0 = xv.x*w0.x + xv.y*w0.y + xv.z*w0.z + xv.w*w0.w;
            float p1 = xv.x*w1.x + xv.y*w1.y + xv.z*w1.z + xv.w*w1.w;
            float p2 = xv.x*w2.x + xv.y*w2.y + xv.z*w2.z + xv.w*w2.w;
            float p3 = xv.x*w3.x + xv.y*w3.y + xv.z*w3.z + xv.w*w3.w;
            p0 = wredsum(p0); p1 = wredsum(p1); p2 = wredsum(p2); p3 = wredsum(p3);
            if (lane < 4) {
                float v = (lane == 0) ? p0 : (lane == 1) ? p1 : (lane == 2) ? p2 : p3;
                g_nk[w * 4 + lane] = v + nkb[lane];
            }
        } else {
            int row = w - NN;
            float2 xv = reinterpret_cast<const float2*>(edge_in + row * FE)[lane];
            float2 w0 = reinterpret_cast<const float2*>(ekW + 0*FE)[lane];
            float2 w1 = reinterpret_cast<const float2*>(ekW + 1*FE)[lane];
            float2 w2 = reinterpret_cast<const float2*>(ekW + 2*FE)[lane];
            float2 w3 = reinterpret_cast<const float2*>(ekW + 3*FE)[lane];
            float p0 = xv.x*w0.x + xv.y*w0.y;
            float p1 = xv.x*w1.x + xv.y*w1.y;
            float p2 = xv.x*w2.x + xv.y*w2.y;
            float p3 = xv.x*w3.x + xv.y*w3.y;
            p0 = wredsum(p0); p1 = wredsum(p1); p2 = wredsum(p2); p3 = wredsum(p3);
            if (lane < 4) {
                float v = (lane == 0) ? p0 : (lane == 1) ? p1 : (lane == 2) ? p2 : p3;
                g_ek[row * 4 + lane] = v + ekb[lane];
            }
        }
    } else {
        int idx = (bid - 640) * 256 + tid;
        if (idx < EE)            atomicAdd(&g_cnt_n[src[idx]], 1);
        else if (idx < EE + NLE) atomicAdd(&g_cnt_e[lg_src[idx - EE]], 1);
    }
}

// ---------------- s1-K1: weight transposes (400 blocks) ----------------
__global__ __launch_bounds__(256)
void trans_kernel(const float* __restrict__ ncW, const float* __restrict__ ecW,
                  const float* __restrict__ nqW, const float* __restrict__ eqW)
{
    int idx = blockIdx.x * 256 + threadIdx.x;     // 0..102399
    if (idx < FN*FN) {
        int o = idx >> 7, f = idx & 127;
        g_ncWT[f*FN + o] = ncW[idx];
    } else if (idx < FN*FN + FE*FE) {
        int i = idx - FN*FN;
        int o = i >> 6, f = i & 63;
        g_ecWT[f*FE + o] = ecW[i];
    } else if (idx < FN*FN + FE*FE + 512*FN) {
        int i = idx - (FN*FN + FE*FE);
        int o = i >> 7, j = i & 127;
        g_nqWT[j*512 + o] = nqW[i];
    } else {
        int i = idx - (FN*FN + FE*FE + 512*FN);
        int o = i >> 6, j = i & 63;
        g_eqWT[j*256 + o] = eqW[i];
    }
}

// ---------------- s1-K2: V gemms (384 blocks) ----------------
__global__ __launch_bounds__(256)
void gemms_kernel(const float* __restrict__ nin, const float* __restrict__ ein,
                  const float* __restrict__ nvW, const float* __restrict__ nvb,
                  const float* __restrict__ evW, const float* __restrict__ evb)
{
    int b = blockIdx.x;
    if (b < 128) {
        gemm_tile(nin, nvW, nvb, g_nv, (b >> 3) * 64, (b & 7) * 64, NH*FN, FN);
    } else {
        b -= 128;
        gemm_tile(ein, evW, evb, g_ev, (b >> 2) * 64, (b & 3) * 64, NH*FE, FE);
    }
}

// ---------------- s0-K2: scans + y/ks (R5's layout) ----------------
__device__ void scan_impl(const int* __restrict__ in, int* __restrict__ out, int items)
{
    __shared__ int sums[1024];
    int tid = threadIdx.x;
    int loc[4];
    int s = 0;
#pragma unroll
    for (int j = 0; j < 4; j++) {
        loc[j] = (j < items) ? in[tid * items + j] : 0;
        s += (j < items) ? loc[j] : 0;
    }
    sums[tid] = s;
    __syncthreads();
    for (int off = 1; off < 1024; off <<= 1) {
        int add = (tid >= off) ? sums[tid - off] : 0;
        __syncthreads();
        sums[tid] += add;
        __syncthreads();
    }
    int run = (tid == 0) ? 0 : sums[tid - 1];
    for (int j = 0; j < items; j++) {
        out[tid * items + j] = run;
        run += loc[j];
    }
    if (tid == 1023) out[1024 * items] = sums[1023];
}

// grid 42 x 1024
__global__ __launch_bounds__(1024)
void scan_y_kernel(const float* __restrict__ node_in, const float* __restrict__ edge_in)
{
    int bid = blockIdx.x, tid = threadIdx.x;
    if (bid == 0)      scan_impl(g_cnt_n, g_off_n, 1);
    else if (bid == 1) scan_impl(g_cnt_e, g_off_e, 4);
    else if (bid < 10) {
        int chunk = bid - 2;
        int h = chunk >> 1;
        int f = tid & 127, part = tid >> 7;
        int m0 = chunk * 128 + part * 16;
        float a0 = 0.f, a1 = 0.f, a2 = 0.f, a3 = 0.f;
        for (int m = m0; m < m0 + 16; m++) {
            float x = node_in[m * FN + f];
            const float* kp = g_nk + m * 4;
            a0 += kp[0]*x; a1 += kp[1]*x; a2 += kp[2]*x; a3 += kp[3]*x;
        }
        atomicAdd(&g_yn[h*512 + 0*FN + f], a0);
        atomicAdd(&g_yn[h*512 + 1*FN + f], a1);
        atomicAdd(&g_yn[h*512 + 2*FN + f], a2);
        atomicAdd(&g_yn[h*512 + 3*FN + f], a3);
        if (f < 4) {
            float s = 0.f;
            for (int m = m0; m < m0 + 16; m++) s += g_nk[m * 4 + f];
            atomicAdd(&g_ksn[h*4 + f], s);
        }
    } else {
        int chunk = bid - 10;
        int h = chunk >> 3;
        int f = tid & 63, part = tid >> 6;
        int m0 = chunk * 128 + part * 8;
        float a0 = 0.f, a1 = 0.f, a2 = 0.f, a3 = 0.f;
        for (int m = m0; m < m0 + 8; m++) {
            float x = edge_in[m * FE + f];
            const float* kp = g_ek + m * 4;
            a0 += kp[0]*x; a1 += kp[1]*x; a2 += kp[2]*x; a3 += kp[3]*x;
        }
        atomicAdd(&g_ye[h*256 + 0*FE + f], a0);
        atomicAdd(&g_ye[h*256 + 1*FE + f], a1);
        atomicAdd(&g_ye[h*256 + 2*FE + f], a2);
        atomicAdd(&g_ye[h*256 + 3*FE + f], a3);
        if (f < 4) {
            float s = 0.f;
            for (int m = m0; m < m0 + 8; m++) s += g_ek[m * 4 + f];
            atomicAdd(&g_kse[h*4 + f], s);
        }
    }
}

// ---------------- s0-K3: CSR fill + t (R5's layout) ----------------
// grid 176 x 256: [0,80) fill, [80,176) t warps (768)
__global__ __launch_bounds__(256)
void fill_t_kernel(const int* __restrict__ src, const int* __restrict__ lg_src,
                   const float* __restrict__ nqW, const float* __restrict__ nqb,
                   const float* __restrict__ eqW, const float* __restrict__ eqb)
{
    int bid = blockIdx.x, tid = threadIdx.x;
    if (bid < 80) {
        int idx = bid * 256 + tid;
        if (idx < EE) {
            int s = src[idx];
            int p = g_off_n[s] + atomicAdd(&g_fc_n[s], 1);
            g_lst_n[p] = idx;
        } else if (idx < EE + NLE) {
            int l = idx - EE;
            int s = lg_src[l];
            int p = g_off_e[s] + atomicAdd(&g_fc_e[s], 1);
            g_lst_e[p] = l;
        }
        return;
    }
    int w = (bid - 80) * 8 + (tid >> 5), lane = tid & 31;
    if (w < 512) {
        int h = w >> 7, f = w & 127;
        float acc = 0.f;
#pragma unroll
        for (int b = 0; b < 4; b++) {
            float4 wv = *reinterpret_cast<const float4*>(&nqW[(size_t)(b*FN + f) * FN + lane*4]);
            float4 yv = *reinterpret_cast<const float4*>(&g_yn[h*512 + b*FN + lane*4]);
            acc += wv.x*yv.x + wv.y*yv.y + wv.z*yv.z + wv.w*yv.w;
        }
        acc = wredsum(acc);
        if (lane == 0) {
            float bt = 0.f;
#pragma unroll
            for (int b = 0; b < 4; b++) bt += nqb[b*FN + f] * g_ksn[h*4 + b];
            g_tn[h*FN + f] = acc + bt;
        }
    } else if (w < 768) {
        int w2 = w - 512;
        int h = w2 >> 6, f = w2 & 63;
        float acc = 0.f;
#pragma unroll
        for (int b = 0; b < 4; b++) {
            float2 wv = *reinterpret_cast<const float2*>(&eqW[(size_t)(b*FE + f) * FE + lane*2]);
            float2 yv = *reinterpret_cast<const float2*>(&g_ye[h*256 + b*FE + lane*2]);
            acc += wv.x*yv.x + wv.y*yv.y;
        }
        acc = wredsum(acc);
        if (lane == 0) {
            float bt = 0.f;
#pragma unroll
            for (int b = 0; b < 4; b++) bt += eqb[b*FE + f] * g_kse[h*4 + b];
            g_te[h*FE + f] = acc + bt;
        }
    }
}

// ---------------- s0-K4: u + c (R5's layout, warp per output) ----------------
// grid 388 x 256
__global__ __launch_bounds__(256)
void uc_kernel(const float* __restrict__ nqb, const float* __restrict__ eqb)
{
    int w = blockIdx.x * 8 + (threadIdx.x >> 5), lane = threadIdx.x & 31;
    if (w < 2048) {
        int h = w >> 9, bq = (w >> 7) & 3, j = w & 127;
        float4 wv = *reinterpret_cast<const float4*>(&g_nqWT[j*512 + bq*FN + lane*4]);
        float4 tv = *reinterpret_cast<const float4*>(&g_tn[h*FN + lane*4]);
        float acc = wv.x*tv.x + wv.y*tv.y + wv.z*tv.z + wv.w*tv.w;
        acc = wredsum(acc);
        if (lane == 0) g_un[h*512 + bq*FN + j] = acc;
    } else if (w < 3072) {
        int w2 = w - 2048;
        int h = w2 >> 8, bq = (w2 >> 6) & 3, j = w2 & 63;
        float2 wv = *reinterpret_cast<const float2*>(&g_eqWT[j*256 + bq*FE + lane*2]);
        float2 tv = *reinterpret_cast<const float2*>(&g_te[h*FE + lane*2]);
        float acc = wv.x*tv.x + wv.y*tv.y;
        acc = wredsum(acc);
        if (lane == 0) g_ue[h*256 + bq*FE + j] = acc;
    } else if (w < 3088) {
        int w3 = w - 3072;
        int h = w3 >> 2, bq = w3 & 3;
        float4 bv = *reinterpret_cast<const float4*>(&nqb[bq*FN + lane*4]);
        float4 tv = *reinterpret_cast<const float4*>(&g_tn[h*FN + lane*4]);
        float acc = bv.x*tv.x + bv.y*tv.y + bv.z*tv.z + bv.w*tv.w;
        acc = wredsum(acc);
        if (lane == 0) g_cn[h*4 + bq] = acc;
    } else if (w < 3104) {
        int w3 = w - 3088;
        int h = w3 >> 2, bq = w3 & 3;
        float2 bv = *reinterpret_cast<const float2*>(&eqb[bq*FE + lane*2]);
        float2 tv = *reinterpret_cast<const float2*>(&g_te[h*FE + lane*2]);
        float acc = bv.x*tv.x + bv.y*tv.y;
        acc = wredsum(acc);
        if (lane == 0) g_ce[h*4 + bq] = acc;
    }
}

// ---------------- s0-K5: raw scores ----------------
__global__ __launch_bounds__(256)
void scores_kernel(const float* __restrict__ node_in, const float* __restrict__ edge_in)
{
    int w = blockIdx.x * 8 + (threadIdx.x >> 5);
    int lane = threadIdx.x & 31;
    if (w < NH*NN) {
        int h = w >> 10, m = w & (NN - 1);
        int a = m >> 2, b = m & 3;
        int row = h * 256 + a;
        float4 uv = *reinterpret_cast<const float4*>(&g_un[h*512 + b*FN + lane*4]);
        float4 xv = *reinterpret_cast<const float4*>(&node_in[row*FN + lane*4]);
        float d = xv.x*uv.x + xv.y*uv.y + xv.z*uv.z + xv.w*uv.w;
        d = wredsum(d);
        if (lane == 0) g_nsa[h*NN + m] = d + g_cn[h*4+b];
    } else {
        int w2 = w - NH*NN;
        int h = w2 >> 12, m = w2 & (EE - 1);
        int a = m >> 2, b = m & 3;
        int row = h * 1024 + a;
        float2 uv = *reinterpret_cast<const float2*>(&g_ue[h*256 + b*FE + lane*2]);
        float2 xv = *reinterpret_cast<const float2*>(&edge_in[row*FE + lane*2]);
        float d = xv.x*uv.x + xv.y*uv.y;
        d = wredsum(d);
        if (lane == 0) g_esa[h*EE + m] = d + g_ce[h*4+b];
    }
}

// ---------------- s0-K6: per-head softmax normalize (in place) ----------------
__global__ __launch_bounds__(1024)
void softmax_kernel()
{
    __shared__ float red[32];
    __shared__ float bc_max, bc_sum;
    int bid = blockIdx.x, tid = threadIdx.x;
    int warp = tid >> 5, lane = tid & 31;
    float* buf; int cnt;
    if (bid < 4) { buf = g_nsa + bid * NN;       cnt = 1; }
    else         { buf = g_esa + (bid - 4) * EE; cnt = 4; }

    float v[4];
    float m = -3e38f;
    for (int j = 0; j < cnt; j++) { v[j] = buf[tid + j*1024]; m = fmaxf(m, v[j]); }
#pragma unroll
    for (int o = 16; o; o >>= 1) m = fmaxf(m, __shfl_xor_sync(0xffffffffu, m, o));
    if (lane == 0) red[warp] = m;
    __syncthreads();
    if (tid == 0) {
        float x = red[0];
        for (int w = 1; w < 32; w++) x = fmaxf(x, red[w]);
        bc_max = x;
    }
    __syncthreads();
    float mx = bc_max;

    float sum = 0.f;
    for (int j = 0; j < cnt; j++) { v[j] = expf(v[j] - mx); sum += v[j]; }
#pragma unroll
    for (int o = 16; o; o >>= 1) sum += __shfl_xor_sync(0xffffffffu, sum, o);
    __syncthreads();
    if (lane == 0) red[warp] = sum;
    __syncthreads();
    if (tid == 0) {
        float x = 0.f;
        for (int w = 0; w < 32; w++) x += red[w];
        bc_sum = x;
    }
    __syncthreads();
    float inv = 1.f / bc_sum;
    for (int j = 0; j < cnt; j++) buf[tid + j*1024] = v[j] * inv;
}

// ---------------- s0-K7: merged outputs + cleanup (R5's layout) ----------------
// grid 2064 x 128: [0,1024) node (4 rows/blk), [1024,2048) edge (16 rows/blk), [2048,2064) cleanup
__global__ __launch_bounds__(128)
void out_kernel(const int* __restrict__ dst, const int* __restrict__ lg_dst,
                const float* __restrict__ ncb, const float* __restrict__ ecb,
                float* __restrict__ out)
{
    int bid = blockIdx.x, tid = threadIdx.x;
    if (bid < 1024) {
        __shared__ float agg[4][FN];
        int h = bid >> 8;
        int i0 = (bid & 255) * 4;
#pragma unroll
        for (int r = 0; r < 4; r++) {
            int i = i0 + r;
            int s0 = g_off_n[i], s1 = g_off_n[i + 1];
            float acc = 0.f;
            for (int p = s0; p < s1; p++) {
                int e = g_lst_n[p];
                int d = dst[e];
                bool win = true;
                for (int p2 = s0; p2 < s1; p2++) {
                    int e2 = g_lst_n[p2];
                    if (e2 > e && dst[e2] == d) win = false;   // last write wins
                }
                if (win) acc += g_esa[h*EE + e] * g_nv[h*(NN*FN) + d*FN + tid];
            }
            agg[r][tid] = acc;
        }
        __syncthreads();
        float b = ncb[tid];
        float a0 = b, a1 = b, a2 = b, a3 = b;
#pragma unroll 4
        for (int f = 0; f < FN; f++) {
            float w = g_ncWT[f*FN + tid];
            a0 += agg[0][f] * w;
            a1 += agg[1][f] * w;
            a2 += agg[2][f] * w;
            a3 += agg[3][f] * w;
        }
        float* o = out + h*(NN*FN) + i0*FN + tid;
        o[0*FN] = fmaxf(a0, 0.f);
        o[1*FN] = fmaxf(a1, 0.f);
        o[2*FN] = fmaxf(a2, 0.f);
        o[3*FN] = fmaxf(a3, 0.f);
    } else if (bid < 2048) {
        __shared__ float agg[16][FE];
        int b = bid - 1024;
        int h = b >> 8;
        int i0 = (b & 255) * 16;
        int col = tid & 63, rg = tid >> 6;
#pragma unroll
        for (int k = 0; k < 8; k++) {
            int lr = rg * 8 + k;
            int i = i0 + lr;
            int s0 = g_off_e[i], s1 = g_off_e[i + 1];
            float acc = 0.f;
            for (int p = s0; p < s1; p++) {
                int l = g_lst_e[p];
                int ld = lg_dst[l];
                bool win = true;
                for (int p2 = s0; p2 < s1; p2++) {
                    int l2 = g_lst_e[p2];
                    if (l2 > l && lg_dst[l2] == ld) win = false;
                }
                if (win) acc += g_ev[h*(EE*FE) + ld*FE + col];
            }
            acc *= g_nsa[h*NN + dst[i]];
            agg[lr][col] = acc;
        }
        __syncthreads();
        float a[8];
        float bb = ecb[col];
#pragma unroll
        for (int k = 0; k < 8; k++) a[k] = bb;
#pragma unroll 4
        for (int f = 0; f < FE; f++) {
            float w = g_ecWT[f*FE + col];
#pragma unroll
            for (int k = 0; k < 8; k++) a[k] += agg[rg*8 + k][f] * w;
        }
#pragma unroll
        for (int k = 0; k < 8; k++) {
            int i = i0 + rg*8 + k;
            out[NODE_OUT_SZ + h*(EE*FE) + i*FE + col] = fmaxf(a[k], 0.f);
        }
    } else {
        // cleanup for next run
        int idx = (bid - 2048) * 128 + tid;       // 0..2047
        for (int i = idx; i < NN; i += 2048) { g_cnt_n[i] = 0; g_fc_n[i] = 0; }
        for (int i = idx; i < EE; i += 2048) { g_cnt_e[i] = 0; g_fc_e[i] = 0; }
        if (idx < NH*512) g_yn[idx] = 0.f;
        if (idx < NH*256) g_ye[idx] = 0.f;
        if (idx < 16) { g_ksn[idx] = 0.f; g_kse[idx] = 0.f; }
    }
}

// ---------------- launcher: forked-stream graph (gemms branch overlaps chain) ----------------
extern "C" void kernel_launch(void* const* d_in, const int* in_sizes, int n_in,
                              void* d_out, int out_size)
{
    const float* node_inputs = (const float*)d_in[0];
    const float* edge_inputs = (const float*)d_in[1];
    const int*   src         = (const int*)d_in[2];
    const int*   dst         = (const int*)d_in[3];
    const int*   lg_src      = (const int*)d_in[4];
    const int*   lg_dst      = (const int*)d_in[5];
    const float* nqW = (const float*)d_in[6];
    const float* nqb = (const float*)d_in[7];
    const float* nkW = (const float*)d_in[8];
    const float* nkb = (const float*)d_in[9];
    const float* nvW = (const float*)d_in[10];
    const float* nvb = (const float*)d_in[11];
    const float* eqW = (const float*)d_in[12];
    const float* eqb = (const float*)d_in[13];
    const float* ekW = (const float*)d_in[14];
    const float* ekb = (const float*)d_in[15];
    const float* evW = (const float*)d_in[16];
    const float* evb = (const float*)d_in[17];
    const float* ncW = (const float*)d_in[18];
    const float* ncb = (const float*)d_in[19];
    const float* ecW = (const float*)d_in[20];
    const float* ecb = (const float*)d_in[21];
    float* out = (float*)d_out;

    static cudaStream_t s1 = nullptr;
    static cudaEvent_t ev_fork = nullptr, ev_tr = nullptr, ev_join = nullptr;
    if (s1 == nullptr) {
        cudaStreamCreateWithFlags(&s1, cudaStreamNonBlocking);
        cudaEventCreateWithFlags(&ev_fork, cudaEventDisableTiming);
        cudaEventCreateWithFlags(&ev_tr,   cudaEventDisableTiming);
        cudaEventCreateWithFlags(&ev_join, cudaEventDisableTiming);
    }

    // fork: branch s1 does transposes + V gemms, overlapping the score chain
    cudaEventRecord(ev_fork, 0);
    cudaStreamWaitEvent(s1, ev_fork, 0);
    trans_kernel<<<400, 256, 0, s1>>>(ncW, ecW, nqW, eqW);
    cudaEventRecord(ev_tr, s1);                       // nqWT/eqWT ready (needed by uc)
    gemms_kernel<<<384, 256, 0, s1>>>(node_inputs, edge_inputs, nvW, nvb, evW, evb);
    cudaEventRecord(ev_join, s1);                     // nv/ev + ncWT/ecWT ready (needed by out)

    // main chain on default stream
    prep_kernel<<<720, 256>>>(node_inputs, edge_inputs, nkW, nkb, ekW, ekb, src, lg_src);
    scan_y_kernel<<<42, 1024>>>(node_inputs, edge_inputs);
    fill_t_kernel<<<176, 256>>>(src, lg_src, nqW, nqb, eqW, eqb);
    cudaStreamWaitEvent(0, ev_tr, 0);
    uc_kernel<<<388, 256>>>(nqb, eqb);
    scores_kernel<<<2560, 256>>>(node_inputs, edge_inputs);
    softmax_kernel<<<8, 1024>>>();
    cudaStreamWaitEvent(0, ev_join, 0);
    out_kernel<<<2064, 128>>>(dst, lg_dst, ncb, ecb, out);
}